// round 1
// baseline (speedup 1.0000x reference)
#include <cuda_runtime.h>

#define BB 16
#define CC 528
#define TT 32
#define HH 28
#define WW 28
#define PLANE (HH*WW)       // 784
#define PLANE4 (PLANE/4)    // 196
#define NROI 256

// 26.5 MB scratch for the temporal-mean feature map (B, C, H, W)
__device__ float g_feat[(size_t)BB * CC * PLANE];

// ---------------------------------------------------------------------------
// Kernel 1: feat[b,c,h,w] = mean_t x[b,c,t,h,w]   (HBM-bound, float4)
// ---------------------------------------------------------------------------
__global__ void tmean_kernel(const float* __restrict__ x) {
    int o = blockIdx.x * blockDim.x + threadIdx.x;   // float4 output index
    const int total = BB * CC * PLANE4;              // 1,655,808
    if (o >= total) return;
    int bc = o / PLANE4;
    int i4 = o - bc * PLANE4;
    const float4* in = (const float4*)x + (size_t)bc * TT * PLANE4 + i4;
    float4 acc = make_float4(0.f, 0.f, 0.f, 0.f);
#pragma unroll
    for (int t = 0; t < TT; t++) {
        float4 v = in[(size_t)t * PLANE4];
        acc.x += v.x; acc.y += v.y; acc.z += v.z; acc.w += v.w;
    }
    const float inv = 1.0f / TT;
    acc.x *= inv; acc.y *= inv; acc.z *= inv; acc.w *= inv;
    ((float4*)g_feat)[(size_t)bc * PLANE4 + i4] = acc;
}

// ---------------------------------------------------------------------------
// Kernel 2: one block per roi.
//   1. Build a 784-entry spatial weight map W in smem (256 samples x 4 corners,
//      weights include validity mask and the global 1/256 averaging factor).
//   2. pooled[c] = dot(W, feat[b,c,:,:])  -- warp-per-channel coalesced GEMV.
//   3. MLP 528 -> 128 (relu) -> 32 -> 1.
// ---------------------------------------------------------------------------
__global__ void roi_head_kernel(const float* __restrict__ bbox,
                                const float* __restrict__ w1,
                                const float* __restrict__ b1,
                                const float* __restrict__ w2,
                                const float* __restrict__ b2,
                                const float* __restrict__ w3,
                                const float* __restrict__ b3,
                                float* __restrict__ out) {
    __shared__ __align__(16) float sW[PLANE];
    __shared__ float pooled[CC];
    __shared__ float h1s[128];
    __shared__ float h2s[32];

    const int r = blockIdx.x;
    const int tid = threadIdx.x;

    // zero the weight map
    for (int i = tid; i < PLANE; i += 256) sW[i] = 0.0f;
    __syncthreads();

    // one thread per sample (16x16 grid)
    {
        const float SCALE = 1.0f / 16.0f;
        float bx1 = bbox[r * 5 + 1] * SCALE - 0.5f;
        float by1 = bbox[r * 5 + 2] * SCALE - 0.5f;
        float bx2 = bbox[r * 5 + 3] * SCALE - 0.5f;
        float by2 = bbox[r * 5 + 4] * SCALE - 0.5f;
        float bw = (bx2 - bx1) * 0.125f;   // /OUT
        float bh = (by2 - by1) * 0.125f;

        int iy = tid >> 4;
        int ix = tid & 15;
        float yy = by1 + (iy + 0.5f) * 0.5f * bh;   // off = (i+0.5)/SR
        float xx = bx1 + (ix + 0.5f) * 0.5f * bw;

        float valid = (yy > -1.0f && yy < (float)HH &&
                       xx > -1.0f && xx < (float)WW) ? (1.0f / 256.0f) : 0.0f;

        float yc = fminf(fmaxf(yy, 0.0f), (float)(HH - 1));
        float xc = fminf(fmaxf(xx, 0.0f), (float)(WW - 1));
        int y0 = (int)floorf(yc);
        int x0 = (int)floorf(xc);
        float ly = yc - (float)y0;
        float lx = xc - (float)x0;
        float hy = 1.0f - ly, hx = 1.0f - lx;
        int y1i = min(y0 + 1, HH - 1);
        int x1i = min(x0 + 1, WW - 1);

        atomicAdd(&sW[y0 * WW + x0 ], hy * hx * valid);
        atomicAdd(&sW[y0 * WW + x1i], hy * lx * valid);
        atomicAdd(&sW[y1i * WW + x0 ], ly * hx * valid);
        atomicAdd(&sW[y1i * WW + x1i], ly * lx * valid);
    }
    __syncthreads();

    // GEMV: warp per channel, lanes stride the 196 float4s of each plane
    const int b = (int)bbox[r * 5 + 0];
    const int wid = tid >> 5;
    const int lane = tid & 31;
    const float4* wmap4 = (const float4*)sW;
    for (int c = wid; c < CC; c += 8) {
        const float4* f4 = (const float4*)(g_feat + ((size_t)b * CC + c) * PLANE);
        float s0 = 0.f, s1 = 0.f, s2 = 0.f, s3 = 0.f;
        for (int i = lane; i < PLANE4; i += 32) {
            float4 a = f4[i];
            float4 wv = wmap4[i];
            s0 += a.x * wv.x; s1 += a.y * wv.y;
            s2 += a.z * wv.z; s3 += a.w * wv.w;
        }
        float s = (s0 + s1) + (s2 + s3);
#pragma unroll
        for (int o = 16; o > 0; o >>= 1) s += __shfl_down_sync(0xffffffffu, s, o);
        if (lane == 0) pooled[c] = s;
    }
    __syncthreads();

    // MLP layer 1: 528 -> 128, relu
    if (tid < 128) {
        float acc = b1[tid];
        const float* wr = w1 + (size_t)tid * CC;
#pragma unroll 4
        for (int c = 0; c < CC; c++) acc += pooled[c] * wr[c];
        h1s[tid] = fmaxf(acc, 0.0f);
    }
    __syncthreads();

    // MLP layer 2: 128 -> 32
    if (tid < 32) {
        float acc = b2[tid];
        const float* wr = w2 + (size_t)tid * 128;
#pragma unroll 4
        for (int k = 0; k < 128; k++) acc += h1s[k] * wr[k];
        h2s[tid] = acc;
    }
    __syncthreads();

    // MLP layer 3: 32 -> 1
    if (tid == 0) {
        float acc = b3[0];
#pragma unroll
        for (int k = 0; k < 32; k++) acc += h2s[k] * w3[k];
        out[r] = acc;
    }
}

// ---------------------------------------------------------------------------
extern "C" void kernel_launch(void* const* d_in, const int* in_sizes, int n_in,
                              void* d_out, int out_size) {
    const float* x    = (const float*)d_in[0];
    const float* bbox = (const float*)d_in[1];
    const float* w1   = (const float*)d_in[2];
    const float* b1   = (const float*)d_in[3];
    const float* w2   = (const float*)d_in[4];
    const float* b2   = (const float*)d_in[5];
    const float* w3   = (const float*)d_in[6];
    const float* b3   = (const float*)d_in[7];
    float* out = (float*)d_out;

    const int total4 = BB * CC * PLANE4;           // 1,655,808
    const int blocks = (total4 + 255) / 256;       // 6468
    tmean_kernel<<<blocks, 256>>>(x);
    roi_head_kernel<<<NROI, 256>>>(bbox, w1, b1, w2, b2, w3, b3, out);
}

// round 2
// speedup vs baseline: 1.4381x; 1.4381x over previous
#include <cuda_runtime.h>

#define BB 16
#define CC 528
#define TT 32
#define HH 28
#define WW 28
#define PLANE (HH*WW)       // 784
#define PLANE4 (PLANE/4)    // 196
#define NROI 256
#define CPB 4               // channels per block in fused kernel

// roi spatial weight maps (include validity mask and 1/256 sample-average and 1/T)
__device__ float g_W[NROI * PLANE];           // 803 KB
__device__ int   g_bidx[NROI];
__device__ float g_pooled[NROI * CC];         // 540 KB

// ---------------------------------------------------------------------------
// Kernel A: build per-roi weight maps. One block per roi, 256 threads = samples.
// ---------------------------------------------------------------------------
__global__ void build_w_kernel(const float* __restrict__ bbox) {
    __shared__ float sW[PLANE];
    const int r = blockIdx.x;
    const int tid = threadIdx.x;

    for (int i = tid; i < PLANE; i += 256) sW[i] = 0.0f;
    __syncthreads();

    const float SCALE = 1.0f / 16.0f;
    float bx1 = bbox[r * 5 + 1] * SCALE - 0.5f;
    float by1 = bbox[r * 5 + 2] * SCALE - 0.5f;
    float bx2 = bbox[r * 5 + 3] * SCALE - 0.5f;
    float by2 = bbox[r * 5 + 4] * SCALE - 0.5f;
    float bw = (bx2 - bx1) * 0.125f;
    float bh = (by2 - by1) * 0.125f;

    int iy = tid >> 4;
    int ix = tid & 15;
    float yy = by1 + (iy + 0.5f) * 0.5f * bh;
    float xx = bx1 + (ix + 0.5f) * 0.5f * bw;

    // weight includes 1/256 (sample mean) and 1/32 (temporal mean)
    float valid = (yy > -1.0f && yy < (float)HH &&
                   xx > -1.0f && xx < (float)WW) ? (1.0f / (256.0f * TT)) : 0.0f;

    float yc = fminf(fmaxf(yy, 0.0f), (float)(HH - 1));
    float xc = fminf(fmaxf(xx, 0.0f), (float)(WW - 1));
    int y0 = (int)floorf(yc);
    int x0 = (int)floorf(xc);
    float ly = yc - (float)y0;
    float lx = xc - (float)x0;
    float hy = 1.0f - ly, hx = 1.0f - lx;
    int y1i = min(y0 + 1, HH - 1);
    int x1i = min(x0 + 1, WW - 1);

    atomicAdd(&sW[y0 * WW + x0 ],  hy * hx * valid);
    atomicAdd(&sW[y0 * WW + x1i],  hy * lx * valid);
    atomicAdd(&sW[y1i * WW + x0 ], ly * hx * valid);
    atomicAdd(&sW[y1i * WW + x1i], ly * lx * valid);
    __syncthreads();

    for (int i = tid; i < PLANE; i += 256) g_W[r * PLANE + i] = sW[i];
    if (tid == 0) g_bidx[r] = (int)bbox[r * 5 + 0];
}

// ---------------------------------------------------------------------------
// Kernel B: fused temporal-sum + roi weighted pooling.
// Block = (batch b, 4 channels). Temporal-sum 4 planes of x into smem,
// then dot against every roi weight map of batch b (4 channels share one
// W load). Writes g_pooled[r][c]. x is read exactly once, coalesced.
// ---------------------------------------------------------------------------
__global__ void fused_pool_kernel(const float* __restrict__ x) {
    __shared__ __align__(16) float4 sAcc[CPB * PLANE4];   // 12.5 KB

    const int b  = blockIdx.y;
    const int c0 = blockIdx.x * CPB;
    const int tid = threadIdx.x;

    // temporal accumulation: 784 float4 slots over 256 threads
    for (int s = tid; s < CPB * PLANE4; s += 256) {
        int ch = s / PLANE4;
        int i4 = s - ch * PLANE4;
        const float4* p = (const float4*)x
                        + ((size_t)(b * CC + c0 + ch) * TT) * PLANE4 + i4;
        float4 a = make_float4(0.f, 0.f, 0.f, 0.f);
#pragma unroll
        for (int t = 0; t < TT; t++) {
            float4 v = p[(size_t)t * PLANE4];
            a.x += v.x; a.y += v.y; a.z += v.z; a.w += v.w;
        }
        sAcc[s] = a;   // note: 1/T is folded into g_W
    }
    __syncthreads();

    // roi dot products: warp per roi (strided), 4 channels share each W load
    const int wid = tid >> 5;
    const int lane = tid & 31;
    for (int r = wid; r < NROI; r += 8) {
        if (g_bidx[r] != b) continue;
        const float4* W4 = (const float4*)(g_W + r * PLANE);
        float s0 = 0.f, s1 = 0.f, s2 = 0.f, s3 = 0.f;
        for (int i = lane; i < PLANE4; i += 32) {
            float4 w = W4[i];
            float4 a0 = sAcc[0 * PLANE4 + i];
            float4 a1 = sAcc[1 * PLANE4 + i];
            float4 a2 = sAcc[2 * PLANE4 + i];
            float4 a3 = sAcc[3 * PLANE4 + i];
            s0 += a0.x * w.x + a0.y * w.y + a0.z * w.z + a0.w * w.w;
            s1 += a1.x * w.x + a1.y * w.y + a1.z * w.z + a1.w * w.w;
            s2 += a2.x * w.x + a2.y * w.y + a2.z * w.z + a2.w * w.w;
            s3 += a3.x * w.x + a3.y * w.y + a3.z * w.z + a3.w * w.w;
        }
#pragma unroll
        for (int o = 16; o > 0; o >>= 1) {
            s0 += __shfl_down_sync(0xffffffffu, s0, o);
            s1 += __shfl_down_sync(0xffffffffu, s1, o);
            s2 += __shfl_down_sync(0xffffffffu, s2, o);
            s3 += __shfl_down_sync(0xffffffffu, s3, o);
        }
        if (lane == 0) {
            float* dst = g_pooled + r * CC + c0;
            dst[0] = s0; dst[1] = s1; dst[2] = s2; dst[3] = s3;
        }
    }
}

// ---------------------------------------------------------------------------
// Kernel C: MLP 528 -> 128 (relu) -> 32 -> 1, one block per roi.
// ---------------------------------------------------------------------------
__global__ void mlp_kernel(const float* __restrict__ w1,
                           const float* __restrict__ b1,
                           const float* __restrict__ w2,
                           const float* __restrict__ b2,
                           const float* __restrict__ w3,
                           const float* __restrict__ b3,
                           float* __restrict__ out) {
    __shared__ float sp[CC];
    __shared__ float h1s[128];
    __shared__ float h2s[32];
    const int r = blockIdx.x;
    const int tid = threadIdx.x;   // 128 threads

    for (int c = tid; c < CC; c += 128) sp[c] = g_pooled[r * CC + c];
    __syncthreads();

    {
        float acc = b1[tid];
        const float* wr = w1 + (size_t)tid * CC;
#pragma unroll 4
        for (int c = 0; c < CC; c++) acc += sp[c] * wr[c];
        h1s[tid] = fmaxf(acc, 0.0f);
    }
    __syncthreads();

    if (tid < 32) {
        float acc = b2[tid];
        const float* wr = w2 + (size_t)tid * 128;
#pragma unroll 4
        for (int k = 0; k < 128; k++) acc += h1s[k] * wr[k];
        h2s[tid] = acc;
    }
    __syncthreads();

    if (tid == 0) {
        float acc = b3[0];
#pragma unroll
        for (int k = 0; k < 32; k++) acc += h2s[k] * w3[k];
        out[r] = acc;
    }
}

// ---------------------------------------------------------------------------
extern "C" void kernel_launch(void* const* d_in, const int* in_sizes, int n_in,
                              void* d_out, int out_size) {
    const float* x    = (const float*)d_in[0];
    const float* bbox = (const float*)d_in[1];
    const float* w1   = (const float*)d_in[2];
    const float* b1   = (const float*)d_in[3];
    const float* w2   = (const float*)d_in[4];
    const float* b2   = (const float*)d_in[5];
    const float* w3   = (const float*)d_in[6];
    const float* b3   = (const float*)d_in[7];
    float* out = (float*)d_out;

    build_w_kernel<<<NROI, 256>>>(bbox);
    dim3 grid(CC / CPB, BB);                 // (132, 16) = 2112 blocks
    fused_pool_kernel<<<grid, 256>>>(x);
    mlp_kernel<<<NROI, 128>>>(w1, b1, w2, b2, w3, b3, out);
}

// round 3
// speedup vs baseline: 1.6630x; 1.1563x over previous
#include <cuda_runtime.h>

#define BB 16
#define CC 528
#define TT 32
#define HH 28
#define WW 28
#define PLANE (HH*WW)       // 784
#define PLANE4 (PLANE/4)    // 196
#define NROI 256
#define CPB 4               // channels per block in fused kernel

// roi spatial weight maps (include validity mask, 1/256 sample mean, 1/T)
__device__ float g_W[NROI * PLANE];           // 803 KB
__device__ float g_pooled[NROI * CC];         // 540 KB

// ---------------------------------------------------------------------------
// Kernel A: build per-roi weight maps. One block per roi, 256 threads = samples.
// ---------------------------------------------------------------------------
__global__ void build_w_kernel(const float* __restrict__ bbox) {
    __shared__ float sW[PLANE];
    const int r = blockIdx.x;
    const int tid = threadIdx.x;

    for (int i = tid; i < PLANE; i += 256) sW[i] = 0.0f;
    __syncthreads();

    const float SCALE = 1.0f / 16.0f;
    float bx1 = bbox[r * 5 + 1] * SCALE - 0.5f;
    float by1 = bbox[r * 5 + 2] * SCALE - 0.5f;
    float bx2 = bbox[r * 5 + 3] * SCALE - 0.5f;
    float by2 = bbox[r * 5 + 4] * SCALE - 0.5f;
    float bw = (bx2 - bx1) * 0.125f;
    float bh = (by2 - by1) * 0.125f;

    int iy = tid >> 4;
    int ix = tid & 15;
    float yy = by1 + (iy + 0.5f) * 0.5f * bh;
    float xx = bx1 + (ix + 0.5f) * 0.5f * bw;

    // weight includes 1/256 (sample mean) and 1/32 (temporal mean)
    float valid = (yy > -1.0f && yy < (float)HH &&
                   xx > -1.0f && xx < (float)WW) ? (1.0f / (256.0f * TT)) : 0.0f;

    float yc = fminf(fmaxf(yy, 0.0f), (float)(HH - 1));
    float xc = fminf(fmaxf(xx, 0.0f), (float)(WW - 1));
    int y0 = (int)floorf(yc);
    int x0 = (int)floorf(xc);
    float ly = yc - (float)y0;
    float lx = xc - (float)x0;
    float hy = 1.0f - ly, hx = 1.0f - lx;
    int y1i = min(y0 + 1, HH - 1);
    int x1i = min(x0 + 1, WW - 1);

    atomicAdd(&sW[y0 * WW + x0 ],  hy * hx * valid);
    atomicAdd(&sW[y0 * WW + x1i],  hy * lx * valid);
    atomicAdd(&sW[y1i * WW + x0 ], ly * hx * valid);
    atomicAdd(&sW[y1i * WW + x1i], ly * lx * valid);
    __syncthreads();

    for (int i = tid; i < PLANE; i += 256) g_W[r * PLANE + i] = sW[i];
}

// ---------------------------------------------------------------------------
// Kernel B: fused temporal-sum + roi weighted pooling.
// Block = (batch b, 4 channels). Temporal-sum 4 planes of x into smem,
// then dot against every roi weight map of batch b (4 channels share one
// W load). Batch indices cached in smem — no dependent global scan.
// ---------------------------------------------------------------------------
__global__ void fused_pool_kernel(const float* __restrict__ x,
                                  const float* __restrict__ bbox) {
    __shared__ __align__(16) float4 sAcc[CPB * PLANE4];   // 12.5 KB
    __shared__ int sBidx[NROI];

    const int b  = blockIdx.y;
    const int c0 = blockIdx.x * CPB;
    const int tid = threadIdx.x;

    // batch index of every roi -> smem (coalesced-ish one-shot)
    sBidx[tid] = (int)bbox[tid * 5];

    // temporal accumulation: 784 float4 slots over 256 threads
    for (int s = tid; s < CPB * PLANE4; s += 256) {
        int ch = s / PLANE4;
        int i4 = s - ch * PLANE4;
        const float4* p = (const float4*)x
                        + ((size_t)(b * CC + c0 + ch) * TT) * PLANE4 + i4;
        float4 a = make_float4(0.f, 0.f, 0.f, 0.f);
#pragma unroll
        for (int t = 0; t < TT; t++) {
            float4 v = p[(size_t)t * PLANE4];
            a.x += v.x; a.y += v.y; a.z += v.z; a.w += v.w;
        }
        sAcc[s] = a;   // 1/T is folded into g_W
    }
    __syncthreads();

    // roi dot products: warp per roi (strided), 4 channels share each W load
    const int wid = tid >> 5;
    const int lane = tid & 31;
    for (int r = wid; r < NROI; r += 8) {
        if (sBidx[r] != b) continue;
        const float4* W4 = (const float4*)(g_W + r * PLANE);
        float s0 = 0.f, s1 = 0.f, s2 = 0.f, s3 = 0.f;
        for (int i = lane; i < PLANE4; i += 32) {
            float4 w = W4[i];
            float4 a0 = sAcc[0 * PLANE4 + i];
            float4 a1 = sAcc[1 * PLANE4 + i];
            float4 a2 = sAcc[2 * PLANE4 + i];
            float4 a3 = sAcc[3 * PLANE4 + i];
            s0 += a0.x * w.x + a0.y * w.y + a0.z * w.z + a0.w * w.w;
            s1 += a1.x * w.x + a1.y * w.y + a1.z * w.z + a1.w * w.w;
            s2 += a2.x * w.x + a2.y * w.y + a2.z * w.z + a2.w * w.w;
            s3 += a3.x * w.x + a3.y * w.y + a3.z * w.z + a3.w * w.w;
        }
#pragma unroll
        for (int o = 16; o > 0; o >>= 1) {
            s0 += __shfl_down_sync(0xffffffffu, s0, o);
            s1 += __shfl_down_sync(0xffffffffu, s1, o);
            s2 += __shfl_down_sync(0xffffffffu, s2, o);
            s3 += __shfl_down_sync(0xffffffffu, s3, o);
        }
        if (lane == 0) {
            float* dst = g_pooled + r * CC + c0;
            dst[0] = s0; dst[1] = s1; dst[2] = s2; dst[3] = s3;
        }
    }
}

// ---------------------------------------------------------------------------
// Kernel C: MLP 528 -> 128 (relu) -> 32 -> 1, one block per roi.
// ---------------------------------------------------------------------------
__global__ void mlp_kernel(const float* __restrict__ w1,
                           const float* __restrict__ b1,
                           const float* __restrict__ w2,
                           const float* __restrict__ b2,
                           const float* __restrict__ w3,
                           const float* __restrict__ b3,
                           float* __restrict__ out) {
    __shared__ float sp[CC];
    __shared__ float h1s[128];
    __shared__ float h2s[32];
    const int r = blockIdx.x;
    const int tid = threadIdx.x;   // 128 threads

    for (int c = tid; c < CC; c += 128) sp[c] = g_pooled[r * CC + c];
    __syncthreads();

    {
        float acc = b1[tid];
        const float4* wr = (const float4*)(w1 + (size_t)tid * CC);
        const float4* sp4 = (const float4*)sp;
#pragma unroll 4
        for (int c = 0; c < CC / 4; c++) {
            float4 wv = wr[c];
            float4 pv = sp4[c];
            acc += pv.x * wv.x + pv.y * wv.y + pv.z * wv.z + pv.w * wv.w;
        }
        h1s[tid] = fmaxf(acc, 0.0f);
    }
    __syncthreads();

    if (tid < 32) {
        float acc = b2[tid];
        const float* wr = w2 + (size_t)tid * 128;
#pragma unroll 4
        for (int k = 0; k < 128; k++) acc += h1s[k] * wr[k];
        h2s[tid] = acc;
    }
    __syncthreads();

    if (tid == 0) {
        float acc = b3[0];
#pragma unroll
        for (int k = 0; k < 32; k++) acc += h2s[k] * w3[k];
        out[r] = acc;
    }
}

// ---------------------------------------------------------------------------
extern "C" void kernel_launch(void* const* d_in, const int* in_sizes, int n_in,
                              void* d_out, int out_size) {
    const float* x    = (const float*)d_in[0];
    const float* bbox = (const float*)d_in[1];
    const float* w1   = (const float*)d_in[2];
    const float* b1   = (const float*)d_in[3];
    const float* w2   = (const float*)d_in[4];
    const float* b2   = (const float*)d_in[5];
    const float* w3   = (const float*)d_in[6];
    const float* b3   = (const float*)d_in[7];
    float* out = (float*)d_out;

    build_w_kernel<<<NROI, 256>>>(bbox);
    dim3 grid(CC / CPB, BB);                 // (132, 16) = 2112 blocks
    fused_pool_kernel<<<grid, 256>>>(x, bbox);
    mlp_kernel<<<NROI, 128>>>(w1, b1, w2, b2, w3, b3, out);
}

// round 4
// speedup vs baseline: 1.8528x; 1.1142x over previous
#include <cuda_runtime.h>

#define BB 16
#define CC 528
#define TT 32
#define HH 28
#define WW 28
#define PLANE (HH*WW)       // 784
#define PLANE4 (PLANE/4)    // 196
#define NROI 256
#define CPB 4               // channels per block in fused kernel

__device__ float g_pooled[NROI * CC];         // 540 KB

// ---------------------------------------------------------------------------
// Kernel 1: fused temporal-sum + roi bilinear pooling, zero global traffic in
// phase 2.
//   Block = (batch b, 4 channels).
//   Phase 0: stage all 256 bboxes into smem (drains behind the stream).
//   Phase 1: temporal-sum 4 channel planes of x into smem (DRAM-bound).
//   Phase 2: per roi of batch b, recompute the 256 bilinear samples in
//            registers and gather corners from smem. LDS+ALU only.
// ---------------------------------------------------------------------------
__global__ void fused_pool_kernel(const float* __restrict__ x,
                                  const float* __restrict__ bbox) {
    __shared__ __align__(16) float sA[CPB * PLANE];   // 12.5 KB, channel-major
    __shared__ float sBox[NROI * 5];                  // 5 KB

    const int b  = blockIdx.y;
    const int c0 = blockIdx.x * CPB;
    const int tid = threadIdx.x;

    // stage bboxes (issued first; latency hidden behind phase 1)
#pragma unroll
    for (int i = tid; i < NROI * 5; i += 256) sBox[i] = bbox[i];

    // phase 1: temporal accumulation, 784 float4 slots over 256 threads
    float4* sA4 = (float4*)sA;
    for (int s = tid; s < CPB * PLANE4; s += 256) {
        int ch = s / PLANE4;
        int i4 = s - ch * PLANE4;
        const float4* p = (const float4*)x
                        + ((size_t)(b * CC + c0 + ch) * TT) * PLANE4 + i4;
        float4 a = make_float4(0.f, 0.f, 0.f, 0.f);
#pragma unroll
        for (int t = 0; t < TT; t++) {
            float4 v = p[(size_t)t * PLANE4];
            a.x += v.x; a.y += v.y; a.z += v.z; a.w += v.w;
        }
        // store layout: channel-major scalar plane sA[ch*784 + p]
        sA4[ch * PLANE4 + i4] = a;
    }
    __syncthreads();

    // phase 2: warp per roi (strided). Each lane handles 8 of the 256 samples.
    const int wid = tid >> 5;
    const int lane = tid & 31;
    const float WNORM = 1.0f / (256.0f * (float)TT);  // sample mean * temporal mean

    for (int r = wid; r < NROI; r += 8) {
        if ((int)sBox[r * 5 + 0] != b) continue;

        const float SCALE = 1.0f / 16.0f;
        float bx1 = sBox[r * 5 + 1] * SCALE - 0.5f;
        float by1 = sBox[r * 5 + 2] * SCALE - 0.5f;
        float bx2 = sBox[r * 5 + 3] * SCALE - 0.5f;
        float by2 = sBox[r * 5 + 4] * SCALE - 0.5f;
        float bw = (bx2 - bx1) * 0.125f;
        float bh = (by2 - by1) * 0.125f;

        float s0 = 0.f, s1 = 0.f, s2 = 0.f, s3 = 0.f;
#pragma unroll
        for (int k = 0; k < 8; k++) {
            int smp = lane + k * 32;
            int iy = smp >> 4;
            int ix = smp & 15;
            float yy = by1 + (iy + 0.5f) * 0.5f * bh;
            float xx = bx1 + (ix + 0.5f) * 0.5f * bw;
            float valid = (yy > -1.0f && yy < (float)HH &&
                           xx > -1.0f && xx < (float)WW) ? WNORM : 0.0f;
            float yc = fminf(fmaxf(yy, 0.0f), (float)(HH - 1));
            float xc = fminf(fmaxf(xx, 0.0f), (float)(WW - 1));
            int y0 = (int)floorf(yc);
            int x0 = (int)floorf(xc);
            float ly = yc - (float)y0;
            float lx = xc - (float)x0;
            float hy = 1.0f - ly, hx = 1.0f - lx;
            int y1i = min(y0 + 1, HH - 1);
            int x1i = min(x0 + 1, WW - 1);

            float w00 = hy * hx * valid;
            float w01 = hy * lx * valid;
            float w10 = ly * hx * valid;
            float w11 = ly * lx * valid;

            int p00 = y0 * WW + x0;
            int p01 = y0 * WW + x1i;
            int p10 = y1i * WW + x0;
            int p11 = y1i * WW + x1i;

            const float* a0 = sA;                  // ch 0
            const float* a1 = sA + PLANE;          // ch 1
            const float* a2 = sA + 2 * PLANE;      // ch 2
            const float* a3 = sA + 3 * PLANE;      // ch 3

            s0 += w00 * a0[p00] + w01 * a0[p01] + w10 * a0[p10] + w11 * a0[p11];
            s1 += w00 * a1[p00] + w01 * a1[p01] + w10 * a1[p10] + w11 * a1[p11];
            s2 += w00 * a2[p00] + w01 * a2[p01] + w10 * a2[p10] + w11 * a2[p11];
            s3 += w00 * a3[p00] + w01 * a3[p01] + w10 * a3[p10] + w11 * a3[p11];
        }
#pragma unroll
        for (int o = 16; o > 0; o >>= 1) {
            s0 += __shfl_down_sync(0xffffffffu, s0, o);
            s1 += __shfl_down_sync(0xffffffffu, s1, o);
            s2 += __shfl_down_sync(0xffffffffu, s2, o);
            s3 += __shfl_down_sync(0xffffffffu, s3, o);
        }
        if (lane == 0) {
            float* dst = g_pooled + r * CC + c0;
            dst[0] = s0; dst[1] = s1; dst[2] = s2; dst[3] = s3;
        }
    }
}

// ---------------------------------------------------------------------------
// Kernel 2: MLP 528 -> 128 (relu) -> 32 -> 1, one block per roi.
// ---------------------------------------------------------------------------
__global__ void mlp_kernel(const float* __restrict__ w1,
                           const float* __restrict__ b1,
                           const float* __restrict__ w2,
                           const float* __restrict__ b2,
                           const float* __restrict__ w3,
                           const float* __restrict__ b3,
                           float* __restrict__ out) {
    __shared__ float sp[CC];
    __shared__ float h1s[128];
    __shared__ float h2s[32];
    const int r = blockIdx.x;
    const int tid = threadIdx.x;   // 128 threads

    for (int c = tid; c < CC; c += 128) sp[c] = g_pooled[r * CC + c];
    __syncthreads();

    {
        float acc = b1[tid];
        const float4* wr = (const float4*)(w1 + (size_t)tid * CC);
        const float4* sp4 = (const float4*)sp;
#pragma unroll 4
        for (int c = 0; c < CC / 4; c++) {
            float4 wv = wr[c];
            float4 pv = sp4[c];
            acc += pv.x * wv.x + pv.y * wv.y + pv.z * wv.z + pv.w * wv.w;
        }
        h1s[tid] = fmaxf(acc, 0.0f);
    }
    __syncthreads();

    if (tid < 32) {
        float acc = b2[tid];
        const float* wr = w2 + (size_t)tid * 128;
#pragma unroll 4
        for (int k = 0; k < 128; k++) acc += h1s[k] * wr[k];
        h2s[tid] = acc;
    }
    __syncthreads();

    if (tid == 0) {
        float acc = b3[0];
#pragma unroll
        for (int k = 0; k < 32; k++) acc += h2s[k] * w3[k];
        out[r] = acc;
    }
}

// ---------------------------------------------------------------------------
extern "C" void kernel_launch(void* const* d_in, const int* in_sizes, int n_in,
                              void* d_out, int out_size) {
    const float* x    = (const float*)d_in[0];
    const float* bbox = (const float*)d_in[1];
    const float* w1   = (const float*)d_in[2];
    const float* b1   = (const float*)d_in[3];
    const float* w2   = (const float*)d_in[4];
    const float* b2   = (const float*)d_in[5];
    const float* w3   = (const float*)d_in[6];
    const float* b3   = (const float*)d_in[7];
    float* out = (float*)d_out;

    dim3 grid(CC / CPB, BB);                 // (132, 16) = 2112 blocks
    fused_pool_kernel<<<grid, 256>>>(x, bbox);
    mlp_kernel<<<NROI, 128>>>(w1, b1, w2, b2, w3, b3, out);
}

// round 7
// speedup vs baseline: 1.8879x; 1.0189x over previous
#include <cuda_runtime.h>

#define BB 16
#define CC 528
#define TT 32
#define HH 28
#define WW 28
#define PLANE (HH*WW)       // 784
#define PLANE4 (PLANE/4)    // 196
#define NROI 256
#define CPB 4               // channels per block in fused kernel

__device__ float g_pooled[NROI * CC];         // 540 KB

// ---------------------------------------------------------------------------
// Kernel 1: fused temporal-sum + roi bilinear pooling.
//   Block = (batch b, 4 channels).
//   Phase 0: stage all 256 bboxes into smem.
//   Phase 1: temporal-sum 4 channel planes of x into smem (streaming loads).
//   Phase 2: per roi of batch b, recompute bilinear samples in registers and
//            gather corners from smem. LDS+ALU only, zero global traffic.
// ---------------------------------------------------------------------------
__global__ void fused_pool_kernel(const float* __restrict__ x,
                                  const float* __restrict__ bbox) {
    __shared__ __align__(16) float sA[CPB * PLANE];   // 12.5 KB, channel-major
    __shared__ float sBox[NROI * 5];                  // 5 KB

    const int b  = blockIdx.y;
    const int c0 = blockIdx.x * CPB;
    const int tid = threadIdx.x;

    // stage bboxes (issued first; latency hidden behind phase 1)
#pragma unroll
    for (int i = tid; i < NROI * 5; i += 256) sBox[i] = bbox[i];

    // phase 1: temporal accumulation, 784 float4 slots over 256 threads
    float4* sA4 = (float4*)sA;
    for (int s = tid; s < CPB * PLANE4; s += 256) {
        int ch = s / PLANE4;
        int i4 = s - ch * PLANE4;
        const float4* p = (const float4*)x
                        + ((size_t)(b * CC + c0 + ch) * TT) * PLANE4 + i4;
        float4 a = make_float4(0.f, 0.f, 0.f, 0.f);
#pragma unroll
        for (int t = 0; t < TT; t++) {
            float4 v = __ldcs(&p[(size_t)t * PLANE4]);   // stream, evict-first
            a.x += v.x; a.y += v.y; a.z += v.z; a.w += v.w;
        }
        sA4[ch * PLANE4 + i4] = a;
    }
    __syncthreads();

    // phase 2: warp per roi (strided). Each lane handles 8 of the 256 samples.
    const int wid = tid >> 5;
    const int lane = tid & 31;
    const float WNORM = 1.0f / (256.0f * (float)TT);  // sample mean * temporal mean

    for (int r = wid; r < NROI; r += 8) {
        if ((int)sBox[r * 5 + 0] != b) continue;

        const float SCALE = 1.0f / 16.0f;
        float bx1 = sBox[r * 5 + 1] * SCALE - 0.5f;
        float by1 = sBox[r * 5 + 2] * SCALE - 0.5f;
        float bx2 = sBox[r * 5 + 3] * SCALE - 0.5f;
        float by2 = sBox[r * 5 + 4] * SCALE - 0.5f;
        float bw = (bx2 - bx1) * 0.125f;
        float bh = (by2 - by1) * 0.125f;

        float s0 = 0.f, s1 = 0.f, s2 = 0.f, s3 = 0.f;
#pragma unroll
        for (int k = 0; k < 8; k++) {
            int smp = lane + k * 32;
            int iy = smp >> 4;
            int ix = smp & 15;
            float yy = by1 + (iy + 0.5f) * 0.5f * bh;
            float xx = bx1 + (ix + 0.5f) * 0.5f * bw;
            float valid = (yy > -1.0f && yy < (float)HH &&
                           xx > -1.0f && xx < (float)WW) ? WNORM : 0.0f;
            float yc = fminf(fmaxf(yy, 0.0f), (float)(HH - 1));
            float xc = fminf(fmaxf(xx, 0.0f), (float)(WW - 1));
            int y0 = (int)floorf(yc);
            int x0 = (int)floorf(xc);
            float ly = yc - (float)y0;
            float lx = xc - (float)x0;
            float hy = 1.0f - ly, hx = 1.0f - lx;
            int y1i = min(y0 + 1, HH - 1);
            int x1i = min(x0 + 1, WW - 1);

            float w00 = hy * hx * valid;
            float w01 = hy * lx * valid;
            float w10 = ly * hx * valid;
            float w11 = ly * lx * valid;

            int p00 = y0 * WW + x0;
            int p01 = y0 * WW + x1i;
            int p10 = y1i * WW + x0;
            int p11 = y1i * WW + x1i;

            const float* a0 = sA;
            const float* a1 = sA + PLANE;
            const float* a2 = sA + 2 * PLANE;
            const float* a3 = sA + 3 * PLANE;

            s0 += w00 * a0[p00] + w01 * a0[p01] + w10 * a0[p10] + w11 * a0[p11];
            s1 += w00 * a1[p00] + w01 * a1[p01] + w10 * a1[p10] + w11 * a1[p11];
            s2 += w00 * a2[p00] + w01 * a2[p01] + w10 * a2[p10] + w11 * a2[p11];
            s3 += w00 * a3[p00] + w01 * a3[p01] + w10 * a3[p10] + w11 * a3[p11];
        }
#pragma unroll
        for (int o = 16; o > 0; o >>= 1) {
            s0 += __shfl_down_sync(0xffffffffu, s0, o);
            s1 += __shfl_down_sync(0xffffffffu, s1, o);
            s2 += __shfl_down_sync(0xffffffffu, s2, o);
            s3 += __shfl_down_sync(0xffffffffu, s3, o);
        }
        if (lane == 0) {
            float* dst = g_pooled + r * CC + c0;
            dst[0] = s0; dst[1] = s1; dst[2] = s2; dst[3] = s3;
        }
    }
}

// ---------------------------------------------------------------------------
// Kernel 2: MLP 528 -> 128 (relu) -> 32 -> 1. One block (256 thr) per roi.
// Warp-per-neuron: lanes stride each w1 row in float4 -> coalesced, L2-hot.
// ---------------------------------------------------------------------------
__global__ void mlp_kernel(const float* __restrict__ w1,
                           const float* __restrict__ b1,
                           const float* __restrict__ w2,
                           const float* __restrict__ b2,
                           const float* __restrict__ w3,
                           const float* __restrict__ b3,
                           float* __restrict__ out) {
    __shared__ __align__(16) float sp[CC];
    __shared__ float h1s[128];
    __shared__ float h2s[32];
    const int r = blockIdx.x;
    const int tid = threadIdx.x;   // 256 threads
    const int wid = tid >> 5;
    const int lane = tid & 31;

    for (int c = tid; c < CC; c += 256) sp[c] = g_pooled[r * CC + c];
    __syncthreads();

    // layer 1: each warp reduces 16 neurons (wid, wid+8, ...)
    const float4* sp4 = (const float4*)sp;
    for (int n = wid; n < 128; n += 8) {
        const float4* wr = (const float4*)(w1 + (size_t)n * CC);
        float acc = 0.0f;
        for (int i = lane; i < CC / 4; i += 32) {   // 132 float4s
            float4 wv = wr[i];
            float4 pv = sp4[i];
            acc += pv.x * wv.x + pv.y * wv.y + pv.z * wv.z + pv.w * wv.w;
        }
#pragma unroll
        for (int o = 16; o > 0; o >>= 1) acc += __shfl_down_sync(0xffffffffu, acc, o);
        if (lane == 0) h1s[n] = fmaxf(acc + b1[n], 0.0f);
    }
    __syncthreads();

    // layer 2: each warp reduces 4 neurons
    for (int n = wid; n < 32; n += 8) {
        const float* wr = w2 + (size_t)n * 128;
        float acc = h1s[lane] * wr[lane] + h1s[lane + 32] * wr[lane + 32]
                  + h1s[lane + 64] * wr[lane + 64] + h1s[lane + 96] * wr[lane + 96];
#pragma unroll
        for (int o = 16; o > 0; o >>= 1) acc += __shfl_down_sync(0xffffffffu, acc, o);
        if (lane == 0) h2s[n] = acc + b2[n];
    }
    __syncthreads();

    // layer 3: warp 0 reduces 32 terms
    if (wid == 0) {
        float acc = h2s[lane] * w3[lane];
#pragma unroll
        for (int o = 16; o > 0; o >>= 1) acc += __shfl_down_sync(0xffffffffu, acc, o);
        if (lane == 0) out[r] = acc + b3[0];
    }
}

// ---------------------------------------------------------------------------
extern "C" void kernel_launch(void* const* d_in, const int* in_sizes, int n_in,
                              void* d_out, int out_size) {
    const float* x    = (const float*)d_in[0];
    const float* bbox = (const float*)d_in[1];
    const float* w1   = (const float*)d_in[2];
    const float* b1   = (const float*)d_in[3];
    const float* w2   = (const float*)d_in[4];
    const float* b2   = (const float*)d_in[5];
    const float* w3   = (const float*)d_in[6];
    const float* b3   = (const float*)d_in[7];
    float* out = (float*)d_out;

    dim3 grid(CC / CPB, BB);                 // (132, 16) = 2112 blocks
    fused_pool_kernel<<<grid, 256>>>(x, bbox);
    mlp_kernel<<<NROI, 256>>>(w1, b1, w2, b2, w3, b3, out);
}

// round 12
// speedup vs baseline: 1.9589x; 1.0376x over previous
#include <cuda_runtime.h>

#define BB 16
#define CC 528
#define TT 32
#define HH 28
#define WW 28
#define PLANE (HH*WW)       // 784
#define PLANE4 (PLANE/4)    // 196
#define NROI 256
#define CPB 4               // channels per block in fused kernel

__device__ float g_pooled[NROI * CC];         // 540 KB
__device__ float g_w1T[CC * 128];             // 270 KB, [c][n]
__device__ float g_w2T[128 * 32];             // 16 KB,  [k][n]

// ---------------------------------------------------------------------------
// Kernel 0: transpose w1 (128x528 -> 528x128) and w2 (32x128 -> 128x32).
// ---------------------------------------------------------------------------
__global__ void transpose_w_kernel(const float* __restrict__ w1,
                                   const float* __restrict__ w2) {
    int i = blockIdx.x * blockDim.x + threadIdx.x;
    if (i < 128 * CC) {
        int n = i / CC;          // coalesced read of w1[n][c]
        int c = i - n * CC;
        g_w1T[c * 128 + n] = w1[i];
    }
    if (i < 32 * 128) {
        int n = i / 128;
        int k = i - n * 128;
        g_w2T[k * 32 + n] = w2[i];
    }
}

// ---------------------------------------------------------------------------
// Kernel 1: fused temporal-sum + roi bilinear pooling (unchanged).
// ---------------------------------------------------------------------------
__global__ void fused_pool_kernel(const float* __restrict__ x,
                                  const float* __restrict__ bbox) {
    __shared__ __align__(16) float sA[CPB * PLANE];   // 12.5 KB, channel-major
    __shared__ float sBox[NROI * 5];                  // 5 KB

    const int b  = blockIdx.y;
    const int c0 = blockIdx.x * CPB;
    const int tid = threadIdx.x;

#pragma unroll
    for (int i = tid; i < NROI * 5; i += 256) sBox[i] = bbox[i];

    float4* sA4 = (float4*)sA;
    for (int s = tid; s < CPB * PLANE4; s += 256) {
        int ch = s / PLANE4;
        int i4 = s - ch * PLANE4;
        const float4* p = (const float4*)x
                        + ((size_t)(b * CC + c0 + ch) * TT) * PLANE4 + i4;
        float4 a = make_float4(0.f, 0.f, 0.f, 0.f);
#pragma unroll
        for (int t = 0; t < TT; t++) {
            float4 v = __ldcs(&p[(size_t)t * PLANE4]);
            a.x += v.x; a.y += v.y; a.z += v.z; a.w += v.w;
        }
        sA4[ch * PLANE4 + i4] = a;
    }
    __syncthreads();

    const int wid = tid >> 5;
    const int lane = tid & 31;
    const float WNORM = 1.0f / (256.0f * (float)TT);

    for (int r = wid; r < NROI; r += 8) {
        if ((int)sBox[r * 5 + 0] != b) continue;

        const float SCALE = 1.0f / 16.0f;
        float bx1 = sBox[r * 5 + 1] * SCALE - 0.5f;
        float by1 = sBox[r * 5 + 2] * SCALE - 0.5f;
        float bx2 = sBox[r * 5 + 3] * SCALE - 0.5f;
        float by2 = sBox[r * 5 + 4] * SCALE - 0.5f;
        float bw = (bx2 - bx1) * 0.125f;
        float bh = (by2 - by1) * 0.125f;

        float s0 = 0.f, s1 = 0.f, s2 = 0.f, s3 = 0.f;
#pragma unroll
        for (int k = 0; k < 8; k++) {
            int smp = lane + k * 32;
            int iy = smp >> 4;
            int ix = smp & 15;
            float yy = by1 + (iy + 0.5f) * 0.5f * bh;
            float xx = bx1 + (ix + 0.5f) * 0.5f * bw;
            float valid = (yy > -1.0f && yy < (float)HH &&
                           xx > -1.0f && xx < (float)WW) ? WNORM : 0.0f;
            float yc = fminf(fmaxf(yy, 0.0f), (float)(HH - 1));
            float xc = fminf(fmaxf(xx, 0.0f), (float)(WW - 1));
            int y0 = (int)floorf(yc);
            int x0 = (int)floorf(xc);
            float ly = yc - (float)y0;
            float lx = xc - (float)x0;
            float hy = 1.0f - ly, hx = 1.0f - lx;
            int y1i = min(y0 + 1, HH - 1);
            int x1i = min(x0 + 1, WW - 1);

            float w00 = hy * hx * valid;
            float w01 = hy * lx * valid;
            float w10 = ly * hx * valid;
            float w11 = ly * lx * valid;

            int p00 = y0 * WW + x0;
            int p01 = y0 * WW + x1i;
            int p10 = y1i * WW + x0;
            int p11 = y1i * WW + x1i;

            const float* a0 = sA;
            const float* a1 = sA + PLANE;
            const float* a2 = sA + 2 * PLANE;
            const float* a3 = sA + 3 * PLANE;

            s0 += w00 * a0[p00] + w01 * a0[p01] + w10 * a0[p10] + w11 * a0[p11];
            s1 += w00 * a1[p00] + w01 * a1[p01] + w10 * a1[p10] + w11 * a1[p11];
            s2 += w00 * a2[p00] + w01 * a2[p01] + w10 * a2[p10] + w11 * a2[p11];
            s3 += w00 * a3[p00] + w01 * a3[p01] + w10 * a3[p10] + w11 * a3[p11];
        }
#pragma unroll
        for (int o = 16; o > 0; o >>= 1) {
            s0 += __shfl_down_sync(0xffffffffu, s0, o);
            s1 += __shfl_down_sync(0xffffffffu, s1, o);
            s2 += __shfl_down_sync(0xffffffffu, s2, o);
            s3 += __shfl_down_sync(0xffffffffu, s3, o);
        }
        if (lane == 0) {
            float* dst = g_pooled + r * CC + c0;
            dst[0] = s0; dst[1] = s1; dst[2] = s2; dst[3] = s3;
        }
    }
}

// ---------------------------------------------------------------------------
// Kernel 2: MLP 528 -> 128 (relu) -> 32 -> 1. One block (256 thr) per roi.
// Thread-per-neuron with TRANSPOSED weights: coalesced loads, no shuffles.
// 256 threads: neuron n = tid & 127, c-half = tid >> 7 (halves the c-loop).
// ---------------------------------------------------------------------------
__global__ void mlp_kernel(const float* __restrict__ b1,
                           const float* __restrict__ b2,
                           const float* __restrict__ w3,
                           const float* __restrict__ b3,
                           float* __restrict__ out) {
    __shared__ __align__(16) float sp[CC];
    __shared__ float part[2][128];
    __shared__ float h1s[128];
    __shared__ float h2s[32];
    const int r = blockIdx.x;
    const int tid = threadIdx.x;   // 256 threads
    const int n = tid & 127;
    const int half = tid >> 7;

    for (int c = tid; c < CC; c += 256) sp[c] = g_pooled[r * CC + c];
    __syncthreads();

    // layer 1: acc over one half of c; coalesced w1T[c*128+n]
    {
        const int cbeg = half * (CC / 2);       // 0 or 264
        const float* wt = g_w1T + (size_t)cbeg * 128 + n;
        float acc = 0.0f;
#pragma unroll 8
        for (int c = 0; c < CC / 2; c++) {
            acc += sp[cbeg + c] * wt[(size_t)c * 128];
        }
        part[half][n] = acc;
    }
    __syncthreads();
    if (half == 0) {
        h1s[n] = fmaxf(part[0][n] + part[1][n] + b1[n], 0.0f);
    }
    __syncthreads();

    // layer 2: 32 neurons, threads 0..31, coalesced w2T[k*32+n]
    if (tid < 32) {
        float acc = b2[tid];
        const float* wt = g_w2T + tid;
#pragma unroll 8
        for (int k = 0; k < 128; k++) {
            acc += h1s[k] * wt[(size_t)k * 32];
        }
        h2s[tid] = acc;
    }
    __syncthreads();

    // layer 3: warp 0 reduces 32 terms
    if (tid < 32) {
        float acc = h2s[tid] * w3[tid];
#pragma unroll
        for (int o = 16; o > 0; o >>= 1) acc += __shfl_down_sync(0xffffffffu, acc, o);
        if (tid == 0) out[r] = acc + b3[0];
    }
}

// ---------------------------------------------------------------------------
extern "C" void kernel_launch(void* const* d_in, const int* in_sizes, int n_in,
                              void* d_out, int out_size) {
    const float* x    = (const float*)d_in[0];
    const float* bbox = (const float*)d_in[1];
    const float* w1   = (const float*)d_in[2];
    const float* b1   = (const float*)d_in[3];
    const float* w2   = (const float*)d_in[4];
    const float* b2   = (const float*)d_in[5];
    const float* w3   = (const float*)d_in[6];
    const float* b3   = (const float*)d_in[7];
    float* out = (float*)d_out;

    transpose_w_kernel<<<(128 * CC + 255) / 256, 256>>>(w1, w2);
    dim3 grid(CC / CPB, BB);                 // (132, 16) = 2112 blocks
    fused_pool_kernel<<<grid, 256>>>(x, bbox);
    mlp_kernel<<<NROI, 256>>>(b1, b2, w3, b3, out);
}

// round 13
// speedup vs baseline: 2.0534x; 1.0482x over previous
#include <cuda_runtime.h>

#define BB 16
#define CC 528
#define TT 32
#define HH 28
#define WW 28
#define PLANE (HH*WW)       // 784
#define PLANE4 (PLANE/4)    // 196
#define NROI 256
#define CPB 4               // channels per block in fused kernel
#define CQ (CC/4)           // 132 channels per mlp1 quarter

__device__ float g_pooled[NROI * CC];         // 540 KB
__device__ float g_w1T[CC * 128];             // 270 KB, [c][n]
__device__ float g_w2T[128 * 32];             // 16 KB,  [k][n]
__device__ float g_h1p[4 * NROI * 128];       // 512 KB, layer-1 partials [q][r][n]

// ---------------------------------------------------------------------------
// Kernel 0: transpose w1 (128x528 -> 528x128) and w2 (32x128 -> 128x32).
// ---------------------------------------------------------------------------
__global__ void transpose_w_kernel(const float* __restrict__ w1,
                                   const float* __restrict__ w2) {
    int i = blockIdx.x * blockDim.x + threadIdx.x;
    if (i < 128 * CC) {
        int n = i / CC;          // coalesced read of w1[n][c]
        int c = i - n * CC;
        g_w1T[c * 128 + n] = w1[i];
    }
    if (i < 32 * 128) {
        int n = i / 128;
        int k = i - n * 128;
        g_w2T[k * 32 + n] = w2[i];
    }
}

// ---------------------------------------------------------------------------
// Kernel 1: fused temporal-sum + roi bilinear pooling (unchanged).
// ---------------------------------------------------------------------------
__global__ void fused_pool_kernel(const float* __restrict__ x,
                                  const float* __restrict__ bbox) {
    __shared__ __align__(16) float sA[CPB * PLANE];   // 12.5 KB, channel-major
    __shared__ float sBox[NROI * 5];                  // 5 KB

    const int b  = blockIdx.y;
    const int c0 = blockIdx.x * CPB;
    const int tid = threadIdx.x;

#pragma unroll
    for (int i = tid; i < NROI * 5; i += 256) sBox[i] = bbox[i];

    float4* sA4 = (float4*)sA;
    for (int s = tid; s < CPB * PLANE4; s += 256) {
        int ch = s / PLANE4;
        int i4 = s - ch * PLANE4;
        const float4* p = (const float4*)x
                        + ((size_t)(b * CC + c0 + ch) * TT) * PLANE4 + i4;
        float4 a = make_float4(0.f, 0.f, 0.f, 0.f);
#pragma unroll
        for (int t = 0; t < TT; t++) {
            float4 v = __ldcs(&p[(size_t)t * PLANE4]);
            a.x += v.x; a.y += v.y; a.z += v.z; a.w += v.w;
        }
        sA4[ch * PLANE4 + i4] = a;
    }
    __syncthreads();

    const int wid = tid >> 5;
    const int lane = tid & 31;
    const float WNORM = 1.0f / (256.0f * (float)TT);

    for (int r = wid; r < NROI; r += 8) {
        if ((int)sBox[r * 5 + 0] != b) continue;

        const float SCALE = 1.0f / 16.0f;
        float bx1 = sBox[r * 5 + 1] * SCALE - 0.5f;
        float by1 = sBox[r * 5 + 2] * SCALE - 0.5f;
        float bx2 = sBox[r * 5 + 3] * SCALE - 0.5f;
        float by2 = sBox[r * 5 + 4] * SCALE - 0.5f;
        float bw = (bx2 - bx1) * 0.125f;
        float bh = (by2 - by1) * 0.125f;

        float s0 = 0.f, s1 = 0.f, s2 = 0.f, s3 = 0.f;
#pragma unroll
        for (int k = 0; k < 8; k++) {
            int smp = lane + k * 32;
            int iy = smp >> 4;
            int ix = smp & 15;
            float yy = by1 + (iy + 0.5f) * 0.5f * bh;
            float xx = bx1 + (ix + 0.5f) * 0.5f * bw;
            float valid = (yy > -1.0f && yy < (float)HH &&
                           xx > -1.0f && xx < (float)WW) ? WNORM : 0.0f;
            float yc = fminf(fmaxf(yy, 0.0f), (float)(HH - 1));
            float xc = fminf(fmaxf(xx, 0.0f), (float)(WW - 1));
            int y0 = (int)floorf(yc);
            int x0 = (int)floorf(xc);
            float ly = yc - (float)y0;
            float lx = xc - (float)x0;
            float hy = 1.0f - ly, hx = 1.0f - lx;
            int y1i = min(y0 + 1, HH - 1);
            int x1i = min(x0 + 1, WW - 1);

            float w00 = hy * hx * valid;
            float w01 = hy * lx * valid;
            float w10 = ly * hx * valid;
            float w11 = ly * lx * valid;

            int p00 = y0 * WW + x0;
            int p01 = y0 * WW + x1i;
            int p10 = y1i * WW + x0;
            int p11 = y1i * WW + x1i;

            const float* a0 = sA;
            const float* a1 = sA + PLANE;
            const float* a2 = sA + 2 * PLANE;
            const float* a3 = sA + 3 * PLANE;

            s0 += w00 * a0[p00] + w01 * a0[p01] + w10 * a0[p10] + w11 * a0[p11];
            s1 += w00 * a1[p00] + w01 * a1[p01] + w10 * a1[p10] + w11 * a1[p11];
            s2 += w00 * a2[p00] + w01 * a2[p01] + w10 * a2[p10] + w11 * a2[p11];
            s3 += w00 * a3[p00] + w01 * a3[p01] + w10 * a3[p10] + w11 * a3[p11];
        }
#pragma unroll
        for (int o = 16; o > 0; o >>= 1) {
            s0 += __shfl_down_sync(0xffffffffu, s0, o);
            s1 += __shfl_down_sync(0xffffffffu, s1, o);
            s2 += __shfl_down_sync(0xffffffffu, s2, o);
            s3 += __shfl_down_sync(0xffffffffu, s3, o);
        }
        if (lane == 0) {
            float* dst = g_pooled + r * CC + c0;
            dst[0] = s0; dst[1] = s1; dst[2] = s2; dst[3] = s3;
        }
    }
}

// ---------------------------------------------------------------------------
// Kernel 2a: MLP layer-1 partials. Block = (c-quarter q, roi r), 128 threads,
// thread-per-neuron, coalesced w1T reads, 4 accumulators for ILP.
// ---------------------------------------------------------------------------
__global__ void mlp1_kernel() {
    __shared__ float sp[CQ];
    const int q = blockIdx.x;       // 0..3
    const int r = blockIdx.y;       // 0..255
    const int n = threadIdx.x;      // 0..127
    const int cbeg = q * CQ;

    for (int c = n; c < CQ; c += 128) sp[c] = g_pooled[r * CC + cbeg + c];
    __syncthreads();

    const float* wt = g_w1T + (size_t)cbeg * 128 + n;
    float a0 = 0.f, a1 = 0.f, a2 = 0.f, a3 = 0.f;
#pragma unroll
    for (int c = 0; c < CQ; c += 4) {
        a0 += sp[c + 0] * wt[(size_t)(c + 0) * 128];
        a1 += sp[c + 1] * wt[(size_t)(c + 1) * 128];
        a2 += sp[c + 2] * wt[(size_t)(c + 2) * 128];
        a3 += sp[c + 3] * wt[(size_t)(c + 3) * 128];
    }
    g_h1p[((size_t)q * NROI + r) * 128 + n] = (a0 + a1) + (a2 + a3);
}

// ---------------------------------------------------------------------------
// Kernel 2b: combine partials + relu, layer 2 (4-way k-split), layer 3.
// 256 blocks x 128 threads.
// ---------------------------------------------------------------------------
__global__ void mlp23_kernel(const float* __restrict__ b1,
                             const float* __restrict__ b2,
                             const float* __restrict__ w3,
                             const float* __restrict__ b3,
                             float* __restrict__ out) {
    __shared__ float h1s[128];
    __shared__ float p2[4][32];
    const int r = blockIdx.x;
    const int tid = threadIdx.x;    // 128

    {
        float v = g_h1p[((size_t)0 * NROI + r) * 128 + tid]
                + g_h1p[((size_t)1 * NROI + r) * 128 + tid]
                + g_h1p[((size_t)2 * NROI + r) * 128 + tid]
                + g_h1p[((size_t)3 * NROI + r) * 128 + tid];
        h1s[tid] = fmaxf(v + b1[tid], 0.0f);
    }
    __syncthreads();

    // layer 2: neuron n = tid&31, k-quarter kq = tid>>5
    {
        const int n = tid & 31;
        const int kq = tid >> 5;
        const float* wt = g_w2T + n;
        float acc = 0.0f;
#pragma unroll
        for (int k = 0; k < 32; k++) {
            int kk = kq * 32 + k;
            acc += h1s[kk] * wt[(size_t)kk * 32];
        }
        p2[kq][n] = acc;
    }
    __syncthreads();

    // layer 3: warp 0
    if (tid < 32) {
        float h2 = p2[0][tid] + p2[1][tid] + p2[2][tid] + p2[3][tid] + b2[tid];
        float acc = h2 * w3[tid];
#pragma unroll
        for (int o = 16; o > 0; o >>= 1) acc += __shfl_down_sync(0xffffffffu, acc, o);
        if (tid == 0) out[r] = acc + b3[0];
    }
}

// ---------------------------------------------------------------------------
extern "C" void kernel_launch(void* const* d_in, const int* in_sizes, int n_in,
                              void* d_out, int out_size) {
    const float* x    = (const float*)d_in[0];
    const float* bbox = (const float*)d_in[1];
    const float* w1   = (const float*)d_in[2];
    const float* b1   = (const float*)d_in[3];
    const float* w2   = (const float*)d_in[4];
    const float* b2   = (const float*)d_in[5];
    const float* w3   = (const float*)d_in[6];
    const float* b3   = (const float*)d_in[7];
    float* out = (float*)d_out;

    transpose_w_kernel<<<(128 * CC + 255) / 256, 256>>>(w1, w2);
    dim3 grid(CC / CPB, BB);                 // (132, 16) = 2112 blocks
    fused_pool_kernel<<<grid, 256>>>(x, bbox);
    dim3 g1(4, NROI);                        // 1024 blocks
    mlp1_kernel<<<g1, 128>>>();
    mlp23_kernel<<<NROI, 128>>>(b1, b2, w3, b3, out);
}

// round 14
// speedup vs baseline: 2.0695x; 1.0079x over previous
#include <cuda_runtime.h>

#define BB 16
#define CC 528
#define TT 32
#define HH 28
#define WW 28
#define PLANE (HH*WW)       // 784
#define PLANE4 (PLANE/4)    // 196
#define NROI 256
#define CPB 4               // channels per block in fused kernel
#define CQ (CC/4)           // 132 channels per mlp1 quarter

__device__ float g_pooled[NROI * CC];         // 540 KB
__device__ float g_w1T[CC * 128];             // 270 KB, [c][n]
__device__ float g_w2T[128 * 32];             // 16 KB,  [k][n]
__device__ float g_h1p[4 * NROI * 128];       // 512 KB, layer-1 partials [q][r][n]
__device__ int   g_cnt[NROI];                 // completion counters (zero-init; tail resets)

// ---------------------------------------------------------------------------
// Kernel 0: transpose w1 (128x528 -> 528x128) and w2 (32x128 -> 128x32).
// ---------------------------------------------------------------------------
__global__ void transpose_w_kernel(const float* __restrict__ w1,
                                   const float* __restrict__ w2) {
    int i = blockIdx.x * blockDim.x + threadIdx.x;
    if (i < 128 * CC) {
        int n = i / CC;          // coalesced read of w1[n][c]
        int c = i - n * CC;
        g_w1T[c * 128 + n] = w1[i];
    }
    if (i < 32 * 128) {
        int n = i / 128;
        int k = i - n * 128;
        g_w2T[k * 32 + n] = w2[i];
    }
}

// ---------------------------------------------------------------------------
// Kernel 1: fused temporal-sum + roi bilinear pooling.
// sA is CHANNEL-INTERLEAVED: one float4 per spatial position = ch0..3.
// Phase 2 gathers each corner with a single LDS.128 (all 4 channels).
// ---------------------------------------------------------------------------
__global__ void fused_pool_kernel(const float* __restrict__ x,
                                  const float* __restrict__ bbox) {
    __shared__ __align__(16) float sAI[PLANE * CPB];  // 12.5 KB, [pos][ch]
    __shared__ float sBox[NROI * 5];                  // 5 KB

    const int b  = blockIdx.y;
    const int c0 = blockIdx.x * CPB;
    const int tid = threadIdx.x;

#pragma unroll
    for (int i = tid; i < NROI * 5; i += 256) sBox[i] = bbox[i];

    // phase 1: temporal accumulation; store transposed into interleaved layout
    for (int s = tid; s < CPB * PLANE4; s += 256) {
        int ch = s / PLANE4;
        int i4 = s - ch * PLANE4;
        const float4* p = (const float4*)x
                        + ((size_t)(b * CC + c0 + ch) * TT) * PLANE4 + i4;
        float4 a = make_float4(0.f, 0.f, 0.f, 0.f);
#pragma unroll
        for (int t = 0; t < TT; t++) {
            float4 v = __ldcs(&p[(size_t)t * PLANE4]);
            a.x += v.x; a.y += v.y; a.z += v.z; a.w += v.w;
        }
        int pos = i4 * 4;
        sAI[(pos + 0) * CPB + ch] = a.x;
        sAI[(pos + 1) * CPB + ch] = a.y;
        sAI[(pos + 2) * CPB + ch] = a.z;
        sAI[(pos + 3) * CPB + ch] = a.w;
    }
    __syncthreads();

    // phase 2: warp per roi. smp = lane + 32k -> ix = lane&15 is loop-invariant.
    const int wid = tid >> 5;
    const int lane = tid & 31;
    const float WNORM = 1.0f / (256.0f * (float)TT);
    const float4* sA4 = (const float4*)sAI;

    for (int r = wid; r < NROI; r += 8) {
        if ((int)sBox[r * 5 + 0] != b) continue;

        const float SCALE = 1.0f / 16.0f;
        float bx1 = sBox[r * 5 + 1] * SCALE - 0.5f;
        float by1 = sBox[r * 5 + 2] * SCALE - 0.5f;
        float bx2 = sBox[r * 5 + 3] * SCALE - 0.5f;
        float by2 = sBox[r * 5 + 4] * SCALE - 0.5f;
        float bw = (bx2 - bx1) * 0.125f;
        float bh = (by2 - by1) * 0.125f;

        // hoisted x-dimension terms (ix = lane & 15, constant over k)
        const int ix = lane & 15;
        float xx = bx1 + (ix + 0.5f) * 0.5f * bw;
        float vx = (xx > -1.0f && xx < (float)WW) ? WNORM : 0.0f;
        float xc = fminf(fmaxf(xx, 0.0f), (float)(WW - 1));
        int   x0 = (int)floorf(xc);
        float lxw = xc - (float)x0;
        float hxw = 1.0f - lxw;
        int   x1i = min(x0 + 1, WW - 1);
        const int iy0 = lane >> 4;   // 0 or 1

        float4 acc = make_float4(0.f, 0.f, 0.f, 0.f);
#pragma unroll
        for (int k = 0; k < 8; k++) {
            int iy = iy0 + 2 * k;
            float yy = by1 + (iy + 0.5f) * 0.5f * bh;
            float vy = (yy > -1.0f && yy < (float)HH) ? vx : 0.0f;
            float yc = fminf(fmaxf(yy, 0.0f), (float)(HH - 1));
            int   y0 = (int)floorf(yc);
            float lyw = yc - (float)y0;
            float hyw = 1.0f - lyw;
            int   y1i = min(y0 + 1, HH - 1);

            float w00 = hyw * hxw * vy;
            float w01 = hyw * lxw * vy;
            float w10 = lyw * hxw * vy;
            float w11 = lyw * lxw * vy;

            float4 v00 = sA4[y0 * WW + x0 ];
            float4 v01 = sA4[y0 * WW + x1i];
            float4 v10 = sA4[y1i * WW + x0 ];
            float4 v11 = sA4[y1i * WW + x1i];

            acc.x += w00 * v00.x + w01 * v01.x + w10 * v10.x + w11 * v11.x;
            acc.y += w00 * v00.y + w01 * v01.y + w10 * v10.y + w11 * v11.y;
            acc.z += w00 * v00.z + w01 * v01.z + w10 * v10.z + w11 * v11.z;
            acc.w += w00 * v00.w + w01 * v01.w + w10 * v10.w + w11 * v11.w;
        }
#pragma unroll
        for (int o = 16; o > 0; o >>= 1) {
            acc.x += __shfl_down_sync(0xffffffffu, acc.x, o);
            acc.y += __shfl_down_sync(0xffffffffu, acc.y, o);
            acc.z += __shfl_down_sync(0xffffffffu, acc.z, o);
            acc.w += __shfl_down_sync(0xffffffffu, acc.w, o);
        }
        if (lane == 0) {
            *(float4*)(g_pooled + r * CC + c0) = acc;
        }
    }
}

// ---------------------------------------------------------------------------
// Kernel 2: MLP. Block = (c-quarter q, roi r), 128 threads, thread-per-neuron.
// The LAST block to finish a roi (atomic counter) computes layers 2+3 inline.
// ---------------------------------------------------------------------------
__global__ void mlp_kernel(const float* __restrict__ b1,
                           const float* __restrict__ b2,
                           const float* __restrict__ w3,
                           const float* __restrict__ b3,
                           float* __restrict__ out) {
    __shared__ float sp[CQ];
    __shared__ float h1s[128];
    __shared__ float p2[4][32];
    __shared__ int sLast;

    const int q = blockIdx.x;       // 0..3
    const int r = blockIdx.y;       // 0..255
    const int n = threadIdx.x;      // 0..127
    const int cbeg = q * CQ;

    for (int c = n; c < CQ; c += 128) sp[c] = g_pooled[r * CC + cbeg + c];
    __syncthreads();

    {
        const float* wt = g_w1T + (size_t)cbeg * 128 + n;
        float a0 = 0.f, a1 = 0.f, a2 = 0.f, a3 = 0.f;
#pragma unroll
        for (int c = 0; c < CQ; c += 4) {
            a0 += sp[c + 0] * wt[(size_t)(c + 0) * 128];
            a1 += sp[c + 1] * wt[(size_t)(c + 1) * 128];
            a2 += sp[c + 2] * wt[(size_t)(c + 2) * 128];
            a3 += sp[c + 3] * wt[(size_t)(c + 3) * 128];
        }
        g_h1p[((size_t)q * NROI + r) * 128 + n] = (a0 + a1) + (a2 + a3);
    }
    __syncthreads();

    // signal completion; last block for this roi runs the tail
    if (n == 0) {
        __threadfence();
        int old = atomicAdd(&g_cnt[r], 1);
        sLast = (old == 3);
    }
    __syncthreads();
    if (!sLast) return;
    __threadfence();   // acquire: make other blocks' g_h1p writes visible

    {
        float v = g_h1p[((size_t)0 * NROI + r) * 128 + n]
                + g_h1p[((size_t)1 * NROI + r) * 128 + n]
                + g_h1p[((size_t)2 * NROI + r) * 128 + n]
                + g_h1p[((size_t)3 * NROI + r) * 128 + n];
        h1s[n] = fmaxf(v + b1[n], 0.0f);
    }
    __syncthreads();

    // layer 2: neuron nn = n&31, k-quarter kq = n>>5
    {
        const int nn = n & 31;
        const int kq = n >> 5;
        const float* wt = g_w2T + nn;
        float acc = 0.0f;
#pragma unroll
        for (int k = 0; k < 32; k++) {
            int kk = kq * 32 + k;
            acc += h1s[kk] * wt[(size_t)kk * 32];
        }
        p2[kq][nn] = acc;
    }
    __syncthreads();

    // layer 3 + counter reset (for next graph replay)
    if (n < 32) {
        float h2 = p2[0][n] + p2[1][n] + p2[2][n] + p2[3][n] + b2[n];
        float acc = h2 * w3[n];
#pragma unroll
        for (int o = 16; o > 0; o >>= 1) acc += __shfl_down_sync(0xffffffffu, acc, o);
        if (n == 0) {
            out[r] = acc + b3[0];
            g_cnt[r] = 0;
        }
    }
}

// ---------------------------------------------------------------------------
extern "C" void kernel_launch(void* const* d_in, const int* in_sizes, int n_in,
                              void* d_out, int out_size) {
    const float* x    = (const float*)d_in[0];
    const float* bbox = (const float*)d_in[1];
    const float* w1   = (const float*)d_in[2];
    const float* b1   = (const float*)d_in[3];
    const float* w2   = (const float*)d_in[4];
    const float* b2   = (const float*)d_in[5];
    const float* w3   = (const float*)d_in[6];
    const float* b3   = (const float*)d_in[7];
    float* out = (float*)d_out;

    transpose_w_kernel<<<(128 * CC + 255) / 256, 256>>>(w1, w2);
    dim3 grid(CC / CPB, BB);                 // (132, 16) = 2112 blocks
    fused_pool_kernel<<<grid, 256>>>(x, bbox);
    dim3 g1(4, NROI);                        // 1024 blocks
    mlp_kernel<<<g1, 128>>>(b1, b2, w3, b3, out);
}